// round 17
// baseline (speedup 1.0000x reference)
#include <cuda_runtime.h>
#include <cuda_fp16.h>
#include <cstdint>

// PackedViterbi (logsumexp semiring) forward — poll/transform warp split.
// theta: [T=256, B=32, S=128, S=128] fp32.  out: [B=32] fp32.
//
// R15 skeleton (32 clusters x 4 CTAs, 256 thr, tagged log-domain DSMEM relay,
// f16 tables, one barrier/step, all 8 warps dot+send) with the pre-barrier
// work split by role: warps 0-3 poll immediately after the send (transit
// fully absorbed); warps 4-7 transform theta stage t+1 into a triple-buffered
// shared f16 E tile (conflict-free lane->column mapping) during the transit.
// The dot reads E from smem (padded rows, <=2-way). wait_group 1 at top makes
// the pre-barrier transform cross-thread safe.

#define NT   256
#define NB   32
#define NS   128
#define SUBS 4
#define RPC  32
#define NTHR 256
#define TILE_BYTES (RPC * NS * 4)    // 16384
#define PIPE 6
#define DIST 4
#define ROWH 136                     // padded halfs per Esm row
#define LOG2E 1.4426950408889634f
#define FULLM 0xffffffffu

static __device__ __forceinline__ float ex2f_(float x) {
    float y; asm("ex2.approx.ftz.f32 %0, %1;" : "=f"(y) : "f"(x)); return y;
}
static __device__ __forceinline__ float lg2f_(float x) {
    float y; asm("lg2.approx.ftz.f32 %0, %1;" : "=f"(y) : "f"(x)); return y;
}
static __device__ __forceinline__ void cp16(unsigned d, const void* s) {
    asm volatile("cp.async.cg.shared.global [%0], [%1], 16;" :: "r"(d), "l"(s));
}
static __device__ __forceinline__ void st_dsmem64(unsigned daddr, unsigned long long v) {
    asm volatile("st.relaxed.cluster.shared::cluster.b64 [%0], %1;"
                 :: "r"(daddr), "l"(v) : "memory");
}
static __device__ __forceinline__ unsigned long long ld_vol64(unsigned addr) {
    unsigned long long v;
    asm volatile("ld.volatile.shared.b64 %0, [%1];" : "=l"(v) : "r"(addr));
    return v;
}
// pack (lo,hi) -> f16x2, then ex2.approx.f16x2 (lo lands in low half)
static __device__ __forceinline__ unsigned ex2h2_(float lo, float hi) {
    unsigned h, r;
    asm("cvt.rn.f16x2.f32 %0, %1, %2;" : "=r"(h) : "f"(hi), "f"(lo));
    asm("ex2.approx.f16x2 %0, %1;" : "=r"(r) : "r"(h));
    return r;
}
static __device__ __forceinline__ unsigned hfma2_(unsigned a, unsigned b, unsigned c) {
    unsigned d;
    asm("fma.rn.f16x2 %0, %1, %2, %3;" : "=r"(d) : "r"(a), "r"(b), "r"(c));
    return d;
}
static __device__ __forceinline__ float2 h2f2_(unsigned h) {
    float lo, hi;
    asm("{\n\t.reg .f16 l, m;\n\tmov.b32 {l, m}, %2;\n\t"
        "cvt.f32.f16 %0, l;\n\tcvt.f32.f16 %1, m;\n\t}"
        : "=f"(lo), "=f"(hi) : "r"(h));
    return make_float2(lo, hi);
}

extern "C" __global__ void __launch_bounds__(NTHR, 1) __cluster_dims__(SUBS, 1, 1)
viterbi_fwd(const float* __restrict__ theta, float* __restrict__ out)
{
    extern __shared__ float4 ring[];                         // PIPE * 1024 float4
    __shared__ __align__(16) unsigned long long sV[2][NS];   // tagged V' packets (fp32 log)
    __shared__ __align__(8) __half sEVh[2][NS];              // exp2(V'-18) tables
    __shared__ __align__(16) __half Esm[3][RPC][ROWH];       // exp2(theta) tiles, f16

    const int tid  = threadIdx.x;
    const int lane = tid & 31;
    const int warp = tid >> 5;
    const int sl   = lane & 7;          // 8 lanes per row (dot)
    const int rg   = lane >> 3;
    const int rowL = (warp << 2) + rg;  // dot row 0..31
    const int bid  = blockIdx.x;
    const int bb   = bid >> 2;          // batch
    const int sub  = bid & 3;           // cluster rank
    const int irow = sub * RPC + rowL;  // global state index i

    unsigned rbase = (unsigned)__cvta_generic_to_shared(ring);
    unsigned vbase = (unsigned)__cvta_generic_to_shared(&sV[0][0]);

    ((unsigned long long*)sV)[tid] = 0ull;
    __syncthreads();
    asm volatile("barrier.cluster.arrive.aligned;" ::: "memory");
    asm volatile("barrier.cluster.wait.aligned;"   ::: "memory");

    unsigned rV[SUBS];
#pragma unroll
    for (int r = 0; r < SUBS; ++r)
        asm("mapa.shared::cluster.u32 %0, %1, %2;" : "=r"(rV[r]) : "r"(vbase), "r"(r));

    const size_t tstride = (size_t)NB * NS * NS;
    const float* base = theta + ((size_t)bb * NS + (size_t)sub * RPC) * NS;

    // ---- prologue: prefetch stages 0..DIST-1; stages 0,1 complete ----
#pragma unroll
    for (int s = 0; s < DIST; ++s) {
        const char* src = (const char*)(base + (size_t)s * tstride);
        unsigned dst = rbase + s * TILE_BYTES;
#pragma unroll
        for (int k2 = 0; k2 < 4; ++k2) {
            int o = (tid + k2 * NTHR) << 4;
            cp16(dst + o, src + o);
        }
        asm volatile("cp.async.commit_group;");
    }
    asm volatile("cp.async.wait_group 2;");
    __syncthreads();

    // transform stage 0 -> Esm[0] (all 256 threads, conflict-free columns)
    {
        const int colq = tid & 31;          // float4 column 0..31
        const int rwb  = (tid >> 5) * 4;    // 4 rows per warp
#pragma unroll
        for (int m = 0; m < 4; ++m) {
            float4 v = ring[(rwb + m) * 32 + colq];
            unsigned pk0 = ex2h2_(v.x * LOG2E, v.y * LOG2E);
            unsigned pk1 = ex2h2_(v.z * LOG2E, v.w * LOG2E);
            *(uint2*)(&Esm[0][rwb + m][colq * 4]) = make_uint2(pk0, pk1);
        }
        if (tid < NS) sEVh[0][tid] = __float2half_rn(3.814697265625e-06f); // 2^-18
    }
    __syncthreads();

    float off = 0.f;

    for (int t = 0; t < NT; ++t) {
        const int par = t & 1;

        // 1. deep wait: own stage t+2 complete (=> t+1 visible CTA-wide
        //    since every thread's wait at step t-1 covered t+1, then barrier)
        asm volatile("cp.async.wait_group 1;");

        // 2a. POLLERS (warps 0-3): poll V_t packet, build f16 ev entry
        if (warp < 4) {
            if (t > 0) {
                unsigned a = vbase + (unsigned)((par * NS + tid) * 8);
                unsigned long long v;
                do { v = ld_vol64(a); } while ((unsigned)(v >> 32) != (unsigned)t);
                sEVh[par][tid] =
                    __float2half_rn(ex2f_(__uint_as_float((unsigned)v) - 18.f));
            }
        } else {
        // 2b. TRANSFORMERS (warps 4-7): stage t+1 -> Esm[(t+1)%3]
            if (t + 1 < NT) {
                const int p    = tid - 128;
                const int colq = p & 31;
                const int rwb  = (p >> 5) * 8;
                const float4* src = ring + ((t + 1) % PIPE) * 1024;
                __half* dstE = &Esm[(t + 1) % 3][0][0];
#pragma unroll
                for (int m = 0; m < 8; ++m) {
                    float4 v = src[(rwb + m) * 32 + colq];
                    unsigned pk0 = ex2h2_(v.x * LOG2E, v.y * LOG2E);
                    unsigned pk1 = ex2h2_(v.z * LOG2E, v.w * LOG2E);
                    *(uint2*)(dstE + (rwb + m) * ROWH + colq * 4) =
                        make_uint2(pk0, pk1);
                }
            }
        }
        __syncthreads();

        float r = (t > 0) ? __uint_as_float((unsigned)ld_vol64(
                                vbase + (unsigned)(par * NS * 8)))
                          : 0.f;
        off += r;

        // 3. dot: E from smem (padded rows), ev table, 8 HFMA2, 3 shfl
        const __half* erow = &Esm[t % 3][0][0] + rowL * ROWH + sl * 4;
        uint2 e0 = *(const uint2*)(erow);
        uint2 e1 = *(const uint2*)(erow + 32);
        uint2 e2 = *(const uint2*)(erow + 64);
        uint2 e3 = *(const uint2*)(erow + 96);
        const __half* tb = sEVh[par];
        uint2 w0 = *(const uint2*)(tb + 4 * sl);
        uint2 w1 = *(const uint2*)(tb + 32 + 4 * sl);
        uint2 w2 = *(const uint2*)(tb + 64 + 4 * sl);
        uint2 w3 = *(const uint2*)(tb + 96 + 4 * sl);
        unsigned acc0 = 0u, acc1 = 0u;
        acc0 = hfma2_(e0.x, w0.x, acc0); acc1 = hfma2_(e0.y, w0.y, acc1);
        acc0 = hfma2_(e1.x, w1.x, acc0); acc1 = hfma2_(e1.y, w1.y, acc1);
        acc0 = hfma2_(e2.x, w2.x, acc0); acc1 = hfma2_(e2.y, w2.y, acc1);
        acc0 = hfma2_(e3.x, w3.x, acc0); acc1 = hfma2_(e3.y, w3.y, acc1);
        float2 f0 = h2f2_(acc0), f1 = h2f2_(acc1);
        float s = (f0.x + f0.y) + (f1.x + f1.y);
        s += __shfl_xor_sync(FULLM, s, 1);
        s += __shfl_xor_sync(FULLM, s, 2);
        s += __shfl_xor_sync(FULLM, s, 4);

        // 4. send V_{t+1} immediately (parallel 4-lane fan-out)
        float vst = lg2f_(s) + 18.f - r;
        if (sl < SUBS) {
            unsigned long long pkt = ((unsigned long long)(unsigned)(t + 1) << 32)
                                   | (unsigned long long)__float_as_uint(vst);
            unsigned voff = (unsigned)((((t + 1) & 1) * NS + irow) * 8);
            st_dsmem64(rV[sl] + voff, pkt);
        }

        // 5. shadow: issue prefetch for stage t+DIST
        if (t + DIST < NT) {
            const char* src = (const char*)(base + (size_t)(t + DIST) * tstride);
            unsigned dst = rbase + ((t + DIST) % PIPE) * TILE_BYTES;
#pragma unroll
            for (int k2 = 0; k2 < 4; ++k2) {
                int o = (tid + k2 * NTHR) << 4;
                cp16(dst + o, src + o);
            }
        }
        asm volatile("cp.async.commit_group;");
    }

    // ---- epilogue: drain tag NT (parity 0), then rank 0 reduces (fp32) ----
    if (tid < NS) {
        unsigned ad = vbase + (unsigned)(tid * 8);
        unsigned long long v;
        do { v = ld_vol64(ad); } while ((unsigned)(v >> 32) != (unsigned)NT);
    }
    __syncthreads();
    if (sub == 0 && warp == 0) {
        float x0 = __uint_as_float((unsigned)sV[0][lane]);
        float x1 = __uint_as_float((unsigned)sV[0][lane + 32]);
        float x2 = __uint_as_float((unsigned)sV[0][lane + 64]);
        float x3 = __uint_as_float((unsigned)sV[0][lane + 96]);
        float s = ex2f_(x0) + ex2f_(x1) + ex2f_(x2) + ex2f_(x3);
#pragma unroll
        for (int o = 16; o; o >>= 1) s += __shfl_xor_sync(FULLM, s, o);
        if (lane == 0)
            out[bb] = 0.6931471805599453f * (off + lg2f_(s));
    }
    asm volatile("barrier.cluster.arrive.aligned;" ::: "memory");
    asm volatile("barrier.cluster.wait.aligned;"   ::: "memory");
}

extern "C" void kernel_launch(void* const* d_in, const int* in_sizes, int n_in,
                              void* d_out, int out_size)
{
    (void)in_sizes; (void)n_in; (void)out_size;
    const float* theta = (const float*)d_in[0];
    float* out = (float*)d_out;

    cudaFuncSetAttribute(viterbi_fwd,
                         cudaFuncAttributeMaxDynamicSharedMemorySize,
                         PIPE * TILE_BYTES);
    viterbi_fwd<<<NB * SUBS, NTHR, PIPE * TILE_BYTES>>>(theta, out);
}